// round 6
// baseline (speedup 1.0000x reference)
#include <cuda_runtime.h>
#include <cuda_bf16.h>
#include <cstdint>

// Problem constants
#define B_  64
#define C_  3
#define H_  224
#define W_  224
#define GH  28
#define GW  28
#define D_  768
#define KD  192                 // C*8*8
#define M_  (B_*GH*GW)          // 50176

#define PX 588                  // x: 2408448 float4 / (588*256) = 16 iters exactly
#define PW 36                   // w: 36864 float4 / (36*256) = 4 iters exactly

// ---- scratch (no cudaMalloc allowed) ----
__device__ float g_partials[PX + PW];
__device__ float g_scales[3];                              // sx, sw, sx*sw
__device__ __nv_bfloat16 g_xq[(size_t)M_ * KD];            // 19.3 MB
__device__ __nv_bfloat16 g_wq[(size_t)D_ * KD];            // 288 KB

// ===========================================================================
// Pass 1: per-block absmax partials (no atomics; 4-way unrolled for MLP)
// ===========================================================================
__device__ __forceinline__ float amax4(float4 v) {
    return fmaxf(fmaxf(fabsf(v.x), fabsf(v.y)), fmaxf(fabsf(v.z), fabsf(v.w)));
}

__global__ void absmax_part_kernel(const float4* __restrict__ x4,
                                   const float4* __restrict__ w4) {
    __shared__ float red[8];
    const float4* p;
    int iters, bid = blockIdx.x, stride;
    if (bid < PX) { p = x4; iters = 4; stride = PX * 256; }        // 4 groups of 4
    else { p = w4; iters = 1; stride = PW * 256; bid -= PX; }      // 1 group of 4
    int i = bid * 256 + threadIdx.x;
    float m = 0.f;
    for (int g = 0; g < iters; g++) {
        float4 v0 = p[i];
        float4 v1 = p[i + stride];
        float4 v2 = p[i + 2 * stride];
        float4 v3 = p[i + 3 * stride];
        m = fmaxf(m, fmaxf(fmaxf(amax4(v0), amax4(v1)),
                           fmaxf(amax4(v2), amax4(v3))));
        i += 4 * stride;
    }
#pragma unroll
    for (int o = 16; o > 0; o >>= 1)
        m = fmaxf(m, __shfl_xor_sync(0xffffffffu, m, o));
    if ((threadIdx.x & 31) == 0) red[threadIdx.x >> 5] = m;
    __syncthreads();
    if (threadIdx.x < 32) {
        float v = (threadIdx.x < 8) ? red[threadIdx.x] : 0.f;
#pragma unroll
        for (int o = 4; o > 0; o >>= 1)
            v = fmaxf(v, __shfl_xor_sync(0xffffffffu, v, o));
        if (threadIdx.x == 0) g_partials[blockIdx.x] = v;
    }
}

// ===========================================================================
// Pass 2: reduce partials -> scales (one block, 640 threads)
// ===========================================================================
__global__ void scale_kernel() {
    __shared__ float redx[20], redw[20];
    int t = threadIdx.x;
    float v = (t < PX + PW) ? g_partials[t] : 0.f;
    float xv = (t < PX) ? v : 0.f;
    float wv = (t >= PX) ? v : 0.f;
#pragma unroll
    for (int o = 16; o > 0; o >>= 1) {
        xv = fmaxf(xv, __shfl_xor_sync(0xffffffffu, xv, o));
        wv = fmaxf(wv, __shfl_xor_sync(0xffffffffu, wv, o));
    }
    if ((t & 31) == 0) { redx[t >> 5] = xv; redw[t >> 5] = wv; }
    __syncthreads();
    if (t < 32) {
        float a = (t < 20) ? redx[t] : 0.f;
        float b = (t < 20) ? redw[t] : 0.f;
#pragma unroll
        for (int o = 16; o > 0; o >>= 1) {
            a = fmaxf(a, __shfl_xor_sync(0xffffffffu, a, o));
            b = fmaxf(b, __shfl_xor_sync(0xffffffffu, b, o));
        }
        if (t == 0) {
            float sx = fmaxf(a, 1e-8f) / 127.0f;
            float sw = fmaxf(b, 1e-8f) / 127.0f;
            g_scales[0] = sx;
            g_scales[1] = sw;
            g_scales[2] = sx * sw;
        }
    }
}

// ===========================================================================
// Pass 3: quantize w (copy) + x (patchify) -> bf16, one launch, coalesced
// ===========================================================================
__device__ __forceinline__ float fq(float v, float s) {
    return rintf(fminf(fmaxf(v / s, -127.f), 127.f));
}
__device__ __forceinline__ unsigned int pack2(float a, float b, float s) {
    __nv_bfloat162 h = __floats2bfloat162_rn(fq(a, s), fq(b, s));
    return *reinterpret_cast<unsigned int*>(&h);
}

#define WQBLOCKS 144   // 144*256 = 36864 = D_*KD/4
#define XQBLOCKS 4704  // 4704*256 = 1204224 = B_*C_*H_*GW

__global__ void quant_kernel(const float* __restrict__ x,
                             const float* __restrict__ w) {
    int bid = blockIdx.x;
    if (bid < WQBLOCKS) {
        float s = g_scales[1];
        int i = bid * 256 + threadIdx.x;
        float4 v = reinterpret_cast<const float4*>(w)[i];
        uint2 o;
        o.x = pack2(v.x, v.y, s);
        o.y = pack2(v.z, v.w, s);
        reinterpret_cast<uint2*>(g_wq)[i] = o;
    } else {
        float s = g_scales[0];
        int tid = (bid - WQBLOCKS) * 256 + threadIdx.x;
        int wb = tid % GW;
        int h  = (tid / GW) % H_;
        int c  = (tid / (GW * H_)) % C_;
        int b  = tid / (GW * H_ * C_);
        const float4* src = reinterpret_cast<const float4*>(
            x + ((((size_t)b * C_ + c) * H_ + h) * W_ + (size_t)wb * 8));
        float4 v0 = src[0], v1 = src[1];
        int xb = h >> 3, p = h & 7;
        size_t m = (size_t)b * (GH * GW) + (size_t)xb * GW + wb;
        size_t k = (size_t)c * 64 + (size_t)p * 8;
        uint4 o;
        o.x = pack2(v0.x, v0.y, s);
        o.y = pack2(v0.z, v0.w, s);
        o.z = pack2(v1.x, v1.y, s);
        o.w = pack2(v1.z, v1.w, s);
        *reinterpret_cast<uint4*>(g_xq + m * KD + k) = o;
    }
}

// ===========================================================================
// Pass 4: GEMM. out[M,768] = (xq @ wq^T) * s + bias
// CTA tile 128(M) x 128(N), K=192 staged once (pad stride 200 bf16).
// 4 warps (128 threads), warp tile 64(M) x 64(N): per k-step 8 LDSM.x4 feed
// 32 fully independent HMMAs (MMA:LDSM = 4.0, half the LDSM of R5).
// ===========================================================================
#define SSTRIDE 200                      // bf16 elems per smem row (400 B)
#define A_OFF   0
#define B_OFF   (128 * SSTRIDE * 2)      // 51200 B
#define BIAS_OFF (2 * 128 * SSTRIDE * 2) // 102400 B
#define GEMM_SMEM (BIAS_OFF + 512)

__device__ __forceinline__ uint32_t smem_u32(const void* p) {
    uint32_t a;
    asm("{ .reg .u64 t; cvta.to.shared.u64 t, %1; cvt.u32.u64 %0, t; }"
        : "=r"(a) : "l"(p));
    return a;
}

__global__ void __launch_bounds__(128, 2)
gemm_kernel(const float* __restrict__ bias, float* __restrict__ out) {
    extern __shared__ char smem[];
    char* a_ptr = smem + A_OFF;
    char* b_ptr = smem + B_OFF;
    float* bias_s = reinterpret_cast<float*>(smem + BIAS_OFF);

    const int tid = threadIdx.x;
    const int bn = blockIdx.x;   // 0..5
    const int bm = blockIdx.y;   // 0..391
    const float s = g_scales[2];

    bias_s[tid] = bias[bn * 128 + tid];

    // ---- stage A,B tiles: coalesced uint4 from g_xq / g_wq ----
    const uint4* gA = reinterpret_cast<const uint4*>(g_xq + (size_t)bm * 128 * KD);
    const uint4* gB = reinterpret_cast<const uint4*>(g_wq + (size_t)bn * 128 * KD);
#pragma unroll
    for (int it = 0; it < 24; it++) {
        int cid = tid + it * 128;            // 0..3071
        int row = cid / 24, cc = cid % 24;   // 16B vector within 192-elem row
        char* da = a_ptr + row * (SSTRIDE * 2) + cc * 16;
        char* db = b_ptr + row * (SSTRIDE * 2) + cc * 16;
        *reinterpret_cast<uint4*>(da) = gA[cid];
        *reinterpret_cast<uint4*>(db) = gB[cid];
    }
    __syncthreads();

    // ---- MMA mainloop: warp tile 64x64 ----
    const int warp = tid >> 5, lane = tid & 31;
    const int wm = warp & 1;   // M sub-tile (64 rows)
    const int wn = warp >> 1;  // N sub-tile (64 cols)

    float acc[4][8][4];
#pragma unroll
    for (int i = 0; i < 4; i++)
#pragma unroll
        for (int j = 0; j < 8; j++)
#pragma unroll
            for (int r = 0; r < 4; r++) acc[i][j][r] = 0.f;

    const uint32_t a_smem = smem_u32(a_ptr);
    const uint32_t b_smem = smem_u32(b_ptr);
    // A: row = wm*64 + i*16 + (lane&15); k-half = lane>>4
    const uint32_t a_lane_byte =
        (uint32_t)(wm * 64 + (lane & 15)) * (SSTRIDE * 2) + ((lane >> 4) << 4);
    // B: nrow = wn*64 + jj*16 + (grp>>1)*8 + (lane&7); k-half = grp&1
    const int grp = lane >> 3;
    const uint32_t b_lane_byte =
        (uint32_t)(wn * 64 + ((grp >> 1) << 3) + (lane & 7)) * (SSTRIDE * 2) +
        ((grp & 1) << 4);

#pragma unroll
    for (int ks = 0; ks < 12; ks++) {
        const uint32_t kb = (uint32_t)ks * 32;   // 16 bf16 = 32 B per k-step
        uint32_t a[4][4];
#pragma unroll
        for (int i = 0; i < 4; i++) {
            uint32_t addr = a_smem + a_lane_byte + (uint32_t)i * (16 * SSTRIDE * 2) + kb;
            asm volatile(
                "ldmatrix.sync.aligned.m8n8.x4.shared.b16 {%0,%1,%2,%3}, [%4];"
                : "=r"(a[i][0]), "=r"(a[i][1]), "=r"(a[i][2]), "=r"(a[i][3])
                : "r"(addr));
        }
#pragma unroll
        for (int jj = 0; jj < 4; jj++) {
            uint32_t bq[4];
            uint32_t addr = b_smem + b_lane_byte + (uint32_t)jj * (16 * SSTRIDE * 2) + kb;
            asm volatile(
                "ldmatrix.sync.aligned.m8n8.x4.shared.b16 {%0,%1,%2,%3}, [%4];"
                : "=r"(bq[0]), "=r"(bq[1]), "=r"(bq[2]), "=r"(bq[3])
                : "r"(addr));
#pragma unroll
            for (int i = 0; i < 4; i++) {
                asm volatile(
                    "mma.sync.aligned.m16n8k16.row.col.f32.bf16.bf16.f32 "
                    "{%0,%1,%2,%3}, {%4,%5,%6,%7}, {%8,%9}, {%0,%1,%2,%3};\n"
                    : "+f"(acc[i][jj*2][0]), "+f"(acc[i][jj*2][1]),
                      "+f"(acc[i][jj*2][2]), "+f"(acc[i][jj*2][3])
                    : "r"(a[i][0]), "r"(a[i][1]), "r"(a[i][2]), "r"(a[i][3]),
                      "r"(bq[0]), "r"(bq[1]));
                asm volatile(
                    "mma.sync.aligned.m16n8k16.row.col.f32.bf16.bf16.f32 "
                    "{%0,%1,%2,%3}, {%4,%5,%6,%7}, {%8,%9}, {%0,%1,%2,%3};\n"
                    : "+f"(acc[i][jj*2+1][0]), "+f"(acc[i][jj*2+1][1]),
                      "+f"(acc[i][jj*2+1][2]), "+f"(acc[i][jj*2+1][3])
                    : "r"(a[i][0]), "r"(a[i][1]), "r"(a[i][2]), "r"(a[i][3]),
                      "r"(bq[2]), "r"(bq[3]));
            }
        }
    }

    // ---- epilogue: scale + bias, float2 stores ----
    const int g = lane >> 2, t = lane & 3;
    const int m_base = bm * 128 + wm * 64;
    const int n_base = bn * 128 + wn * 64;
#pragma unroll
    for (int i = 0; i < 4; i++) {
        int row0 = m_base + i * 16 + g;
#pragma unroll
        for (int j = 0; j < 8; j++) {
            int col = n_base + j * 8 + t * 2;
            int lcol = wn * 64 + j * 8 + t * 2;
            float2 bv = *reinterpret_cast<const float2*>(&bias_s[lcol]);
            float2 v0 = make_float2(acc[i][j][0] * s + bv.x,
                                    acc[i][j][1] * s + bv.y);
            float2 v1 = make_float2(acc[i][j][2] * s + bv.x,
                                    acc[i][j][3] * s + bv.y);
            *reinterpret_cast<float2*>(&out[(size_t)row0 * D_ + col]) = v0;
            *reinterpret_cast<float2*>(&out[(size_t)(row0 + 8) * D_ + col]) = v1;
        }
    }
}

// ===========================================================================
extern "C" void kernel_launch(void* const* d_in, const int* in_sizes, int n_in,
                              void* d_out, int out_size) {
    (void)in_sizes; (void)n_in; (void)out_size;
    const float* x = (const float*)d_in[0];
    const float* w = (const float*)d_in[1];
    const float* b = (const float*)d_in[2];
    float* out = (float*)d_out;

    absmax_part_kernel<<<PX + PW, 256>>>((const float4*)x, (const float4*)w);
    scale_kernel<<<1, 640>>>();
    quant_kernel<<<WQBLOCKS + XQBLOCKS, 256>>>(x, w);

    cudaFuncSetAttribute(gemm_kernel,
                         cudaFuncAttributeMaxDynamicSharedMemorySize, GEMM_SMEM);
    dim3 grid(D_ / 128, M_ / 128);  // (6, 392)
    gemm_kernel<<<grid, 128, GEMM_SMEM>>>(b, out);
}

// round 10
// speedup vs baseline: 1.0691x; 1.0691x over previous
#include <cuda_runtime.h>
#include <cuda_bf16.h>
#include <cstdint>

// Problem constants
#define B_  64
#define C_  3
#define H_  224
#define W_  224
#define GH  28
#define GW  28
#define D_  768
#define KD  192                 // C*8*8
#define M_  (B_*GH*GW)          // 50176

#define PX 1176                 // x: 2408448 float4 / (1176*256) = 8 per thread
#define PW 36                   // w: 36864 float4 / (36*256) = 4 per thread

// ---- scratch (no cudaMalloc allowed) ----
__device__ float g_partials[PX];
__device__ float g_wpart[PW];
__device__ float g_scales[3];                              // sx, sw, sx*sw
__device__ __nv_bfloat16 g_xq[(size_t)M_ * KD];            // 19.3 MB
__device__ __nv_bfloat16 g_wq[(size_t)D_ * KD];            // 288 KB

// ===========================================================================
// Pass 1: per-block absmax partials (no atomics; MLP-4 unrolled)
// ===========================================================================
__device__ __forceinline__ float amax4(float4 v) {
    return fmaxf(fmaxf(fabsf(v.x), fabsf(v.y)), fmaxf(fabsf(v.z), fabsf(v.w)));
}

__global__ void absmax_part_kernel(const float4* __restrict__ x4,
                                   const float4* __restrict__ w4) {
    __shared__ float red[8];
    const float4* p;
    int iters, bid = blockIdx.x, stride;
    bool isx = bid < PX;
    if (isx) { p = x4; iters = 2; stride = PX * 256; }         // 2 groups of 4
    else { p = w4; iters = 1; stride = PW * 256; bid -= PX; }  // 1 group of 4
    int i = bid * 256 + threadIdx.x;
    float m = 0.f;
    for (int g = 0; g < iters; g++) {
        float4 v0 = p[i];
        float4 v1 = p[i + stride];
        float4 v2 = p[i + 2 * stride];
        float4 v3 = p[i + 3 * stride];
        m = fmaxf(m, fmaxf(fmaxf(amax4(v0), amax4(v1)),
                           fmaxf(amax4(v2), amax4(v3))));
        i += 4 * stride;
    }
#pragma unroll
    for (int o = 16; o > 0; o >>= 1)
        m = fmaxf(m, __shfl_xor_sync(0xffffffffu, m, o));
    if ((threadIdx.x & 31) == 0) red[threadIdx.x >> 5] = m;
    __syncthreads();
    if (threadIdx.x < 32) {
        float v = (threadIdx.x < 8) ? red[threadIdx.x] : 0.f;
#pragma unroll
        for (int o = 4; o > 0; o >>= 1)
            v = fmaxf(v, __shfl_xor_sync(0xffffffffu, v, o));
        if (threadIdx.x == 0) {
            if (isx) g_partials[blockIdx.x] = v;
            else g_wpart[bid] = v;
        }
    }
}

// ===========================================================================
// Pass 2: reduce partials -> scales (one block, 1024 threads)
// ===========================================================================
__global__ void scale_kernel() {
    __shared__ float red[32];
    int t = threadIdx.x;
    float xv = g_partials[t < PX ? t : 0];
    if (t < PX - 1024) xv = fmaxf(xv, g_partials[1024 + t]);
#pragma unroll
    for (int o = 16; o > 0; o >>= 1)
        xv = fmaxf(xv, __shfl_xor_sync(0xffffffffu, xv, o));
    if ((t & 31) == 0) red[t >> 5] = xv;
    __syncthreads();
    if (t < 32) {
        float a = red[t];
#pragma unroll
        for (int o = 16; o > 0; o >>= 1)
            a = fmaxf(a, __shfl_xor_sync(0xffffffffu, a, o));
        float b = (t < PW) ? g_wpart[t] : 0.f;
        if (t + 32 < PW) b = fmaxf(b, g_wpart[t + 32]);
#pragma unroll
        for (int o = 16; o > 0; o >>= 1)
            b = fmaxf(b, __shfl_xor_sync(0xffffffffu, b, o));
        if (t == 0) {
            float sx = fmaxf(a, 1e-8f) / 127.0f;
            float sw = fmaxf(b, 1e-8f) / 127.0f;
            g_scales[0] = sx;
            g_scales[1] = sw;
            g_scales[2] = sx * sw;
        }
    }
}

// ===========================================================================
// Pass 3: quantize w (copy) + x (patchify) -> bf16, one launch, coalesced
// ===========================================================================
__device__ __forceinline__ float fq(float v, float s) {
    return rintf(fminf(fmaxf(v / s, -127.f), 127.f));
}
__device__ __forceinline__ unsigned int pack2(float a, float b, float s) {
    __nv_bfloat162 h = __floats2bfloat162_rn(fq(a, s), fq(b, s));
    return *reinterpret_cast<unsigned int*>(&h);
}

#define WQBLOCKS 144   // 144*256 = 36864 = D_*KD/4
#define XQBLOCKS 4704  // 4704*256 = 1204224 = B_*C_*H_*GW

__global__ void quant_kernel(const float* __restrict__ x,
                             const float* __restrict__ w) {
    int bid = blockIdx.x;
    if (bid < WQBLOCKS) {
        float s = g_scales[1];
        int i = bid * 256 + threadIdx.x;
        float4 v = reinterpret_cast<const float4*>(w)[i];
        uint2 o;
        o.x = pack2(v.x, v.y, s);
        o.y = pack2(v.z, v.w, s);
        reinterpret_cast<uint2*>(g_wq)[i] = o;
    } else {
        float s = g_scales[0];
        int tid = (bid - WQBLOCKS) * 256 + threadIdx.x;
        int wb = tid % GW;
        int h  = (tid / GW) % H_;
        int c  = (tid / (GW * H_)) % C_;
        int b  = tid / (GW * H_ * C_);
        const float4* src = reinterpret_cast<const float4*>(
            x + ((((size_t)b * C_ + c) * H_ + h) * W_ + (size_t)wb * 8));
        float4 v0 = src[0], v1 = src[1];
        int xb = h >> 3, p = h & 7;
        size_t m = (size_t)b * (GH * GW) + (size_t)xb * GW + wb;
        size_t k = (size_t)c * 64 + (size_t)p * 8;
        uint4 o;
        o.x = pack2(v0.x, v0.y, s);
        o.y = pack2(v0.z, v0.w, s);
        o.z = pack2(v1.x, v1.y, s);
        o.w = pack2(v1.z, v1.w, s);
        *reinterpret_cast<uint4*>(g_xq + m * KD + k) = o;
    }
}

// ===========================================================================
// Pass 4: GEMM. out[M,768] = (xq @ wq^T) * s + bias
// Grid (2, 392): each CTA stages A (128x192) ONCE via cp.async and loops
// over 3 bn tiles of 128 cols; B staged via cp.async, next-B fetch
// overlapped with current epilogue. 8 warps, warp tile 32x64 (R5 shape),
// ldmatrix.x4 + mma.sync m16n8k16 bf16. 2 CTA/SM.
// ===========================================================================
#define SSTRIDE 200                      // bf16 elems per smem row (400 B)
#define A_OFF   0
#define B_OFF   (128 * SSTRIDE * 2)      // 51200 B
#define BIAS_OFF (2 * 128 * SSTRIDE * 2) // 102400 B
#define GEMM_SMEM (BIAS_OFF + 2048)

__device__ __forceinline__ uint32_t smem_u32(const void* p) {
    uint32_t a;
    asm("{ .reg .u64 t; cvta.to.shared.u64 t, %1; cvt.u32.u64 %0, t; }"
        : "=r"(a) : "l"(p));
    return a;
}
__device__ __forceinline__ void cp16(uint32_t dst, const void* src) {
    asm volatile("cp.async.cg.shared.global [%0], [%1], 16;"
                 :: "r"(dst), "l"(src));
}
__device__ __forceinline__ void cp_commit() {
    asm volatile("cp.async.commit_group;" ::: "memory");
}
__device__ __forceinline__ void cp_wait0() {
    asm volatile("cp.async.wait_group 0;" ::: "memory");
}

__global__ void __launch_bounds__(256, 2)
gemm_kernel(const float* __restrict__ bias, float* __restrict__ out) {
    extern __shared__ char smem[];
    char* a_ptr = smem + A_OFF;
    char* b_ptr = smem + B_OFF;
    float* bias_s = reinterpret_cast<float*>(smem + BIAS_OFF);

    const int tid = threadIdx.x;
    const int bh = blockIdx.x;   // 0..1  (bn half: 3 tiles each)
    const int bm = blockIdx.y;   // 0..391
    const int bn0 = bh * 3;
    const float s = g_scales[2];

    // bias for this CTA's 384 columns
    bias_s[tid] = bias[bh * 384 + tid];
    if (tid < 128) bias_s[256 + tid] = bias[bh * 384 + 256 + tid];

    const uint32_t a_s = smem_u32(a_ptr);
    const uint32_t b_s = smem_u32(b_ptr);

    // stage A once + B(0) via cp.async
    const uint4* gA = reinterpret_cast<const uint4*>(g_xq + (size_t)bm * 128 * KD);
    const uint4* gB0 = reinterpret_cast<const uint4*>(g_wq + (size_t)bn0 * 128 * KD);
#pragma unroll
    for (int it = 0; it < 12; it++) {
        int cid = tid + it * 256;            // 0..3071
        int row = cid / 24, cc = cid % 24;
        uint32_t off = (uint32_t)row * (SSTRIDE * 2) + cc * 16;
        cp16(a_s + off, gA + cid);
        cp16(b_s + off, gB0 + cid);
    }
    cp_commit();
    cp_wait0();
    __syncthreads();

    const int warp = tid >> 5, lane = tid & 31;
    const int wm = warp & 3;   // M sub-tile (32 rows)
    const int wn = warp >> 2;  // N sub-tile (64 cols)

    const uint32_t a_lane_byte =
        (uint32_t)(wm * 32 + (lane & 15)) * (SSTRIDE * 2) + ((lane >> 4) << 4);
    const int grp = lane >> 3;
    const uint32_t b_lane_byte =
        (uint32_t)(wn * 64 + ((grp >> 1) << 3) + (lane & 7)) * (SSTRIDE * 2) +
        ((grp & 1) << 4);
    const int g = lane >> 2, tt = lane & 3;
    const int m_base = bm * 128 + wm * 32;

#pragma unroll 1
    for (int bt = 0; bt < 3; bt++) {
        float acc[2][8][4];
#pragma unroll
        for (int i = 0; i < 2; i++)
#pragma unroll
            for (int j = 0; j < 8; j++)
#pragma unroll
                for (int r = 0; r < 4; r++) acc[i][j][r] = 0.f;

        // ---- mainloop over K ----
#pragma unroll
        for (int ks = 0; ks < 12; ks++) {
            const uint32_t kb = (uint32_t)ks * 32;
            uint32_t a[2][4];
#pragma unroll
            for (int i = 0; i < 2; i++) {
                uint32_t addr = a_s + a_lane_byte + (uint32_t)i * (16 * SSTRIDE * 2) + kb;
                asm volatile(
                    "ldmatrix.sync.aligned.m8n8.x4.shared.b16 {%0,%1,%2,%3}, [%4];"
                    : "=r"(a[i][0]), "=r"(a[i][1]), "=r"(a[i][2]), "=r"(a[i][3])
                    : "r"(addr));
            }
#pragma unroll
            for (int jj = 0; jj < 4; jj++) {
                uint32_t bq[4];
                uint32_t addr = b_s + b_lane_byte + (uint32_t)jj * (16 * SSTRIDE * 2) + kb;
                asm volatile(
                    "ldmatrix.sync.aligned.m8n8.x4.shared.b16 {%0,%1,%2,%3}, [%4];"
                    : "=r"(bq[0]), "=r"(bq[1]), "=r"(bq[2]), "=r"(bq[3])
                    : "r"(addr));
#pragma unroll
                for (int i = 0; i < 2; i++) {
                    asm volatile(
                        "mma.sync.aligned.m16n8k16.row.col.f32.bf16.bf16.f32 "
                        "{%0,%1,%2,%3}, {%4,%5,%6,%7}, {%8,%9}, {%0,%1,%2,%3};\n"
                        : "+f"(acc[i][jj*2][0]), "+f"(acc[i][jj*2][1]),
                          "+f"(acc[i][jj*2][2]), "+f"(acc[i][jj*2][3])
                        : "r"(a[i][0]), "r"(a[i][1]), "r"(a[i][2]), "r"(a[i][3]),
                          "r"(bq[0]), "r"(bq[1]));
                    asm volatile(
                        "mma.sync.aligned.m16n8k16.row.col.f32.bf16.bf16.f32 "
                        "{%0,%1,%2,%3}, {%4,%5,%6,%7}, {%8,%9}, {%0,%1,%2,%3};\n"
                        : "+f"(acc[i][jj*2+1][0]), "+f"(acc[i][jj*2+1][1]),
                          "+f"(acc[i][jj*2+1][2]), "+f"(acc[i][jj*2+1][3])
                        : "r"(a[i][0]), "r"(a[i][1]), "r"(a[i][2]), "r"(a[i][3]),
                          "r"(bq[2]), "r"(bq[3]));
                }
            }
        }

        // all warps done reading Bs; kick off next B fetch (overlaps epilogue)
        __syncthreads();
        if (bt < 2) {
            const uint4* gB = reinterpret_cast<const uint4*>(
                g_wq + (size_t)(bn0 + bt + 1) * 128 * KD);
#pragma unroll
            for (int it = 0; it < 12; it++) {
                int cid = tid + it * 256;
                int row = cid / 24, cc = cid % 24;
                cp16(b_s + (uint32_t)row * (SSTRIDE * 2) + cc * 16, gB + cid);
            }
            cp_commit();
        }

        // ---- epilogue for this bn tile ----
        const int n_base = (bn0 + bt) * 128 + wn * 64;
        const int l_base = bt * 128 + wn * 64;
#pragma unroll
        for (int i = 0; i < 2; i++) {
            int row0 = m_base + i * 16 + g;
#pragma unroll
            for (int j = 0; j < 8; j++) {
                int col = n_base + j * 8 + tt * 2;
                float2 bv = *reinterpret_cast<const float2*>(
                    &bias_s[l_base + j * 8 + tt * 2]);
                float2 v0 = make_float2(acc[i][j][0] * s + bv.x,
                                        acc[i][j][1] * s + bv.y);
                float2 v1 = make_float2(acc[i][j][2] * s + bv.x,
                                        acc[i][j][3] * s + bv.y);
                *reinterpret_cast<float2*>(&out[(size_t)row0 * D_ + col]) = v0;
                *reinterpret_cast<float2*>(&out[(size_t)(row0 + 8) * D_ + col]) = v1;
            }
        }

        if (bt < 2) {
            cp_wait0();
            __syncthreads();
        }
    }
}

// ===========================================================================
extern "C" void kernel_launch(void* const* d_in, const int* in_sizes, int n_in,
                              void* d_out, int out_size) {
    (void)in_sizes; (void)n_in; (void)out_size;
    const float* x = (const float*)d_in[0];
    const float* w = (const float*)d_in[1];
    const float* b = (const float*)d_in[2];
    float* out = (float*)d_out;

    absmax_part_kernel<<<PX + PW, 256>>>((const float4*)x, (const float4*)w);
    scale_kernel<<<1, 1024>>>();
    quant_kernel<<<WQBLOCKS + XQBLOCKS, 256>>>(x, w);

    cudaFuncSetAttribute(gemm_kernel,
                         cudaFuncAttributeMaxDynamicSharedMemorySize, GEMM_SMEM);
    dim3 grid(2, M_ / 128);  // (2, 392)
    gemm_kernel<<<grid, 256, GEMM_SMEM>>>(b, out);
}